// round 9
// baseline (speedup 1.0000x reference)
#include <cuda_runtime.h>

// Temporal-blocked persistent solver, R9: register-pressure relief.
//  - NT=320, PPT=12 -> LBUF=3840 (same geometry/redundancy as R5/R8),
//    state arrays 48 regs/thread, occ-2 budget 102 regs -> no spill wall.
//  - C1-scaled conservative state: R=rho, Ms=C1*mom; derived Vs=C1*v,
//    FPs=C1^2*(rho v^2+P); C1^2 folded into the pow constant.
//  - Static-parity double buffering (time loop unrolled x2), float4 edges,
//    ONE __syncthreads per step.
//  - Early edge publish: boundary cells' fluxes computed and stored before
//    interior flux work, hiding barrier-arrival skew.
//  - No clamps in hot loop; halo garbage advances 1 cell/step, never reaches
//    the stored interior.

#define NT   320
#define PPT  12
#define LBUF (NT * PPT)            // 3840
#define HALO 128
#define TILE (LBUF - 2 * HALO)     // 3584
#define GRID 296

__device__ __forceinline__ float xlg2(float x) {
    float r; asm("lg2.approx.f32 %0, %1;" : "=f"(r) : "f"(x)); return r;
}
__device__ __forceinline__ float xex2(float x) {
    float r; asm("ex2.approx.f32 %0, %1;" : "=f"(r) : "f"(x)); return r;
}
__device__ __forceinline__ float xrcp(float x) {
    float r; asm("rcp.approx.f32 %0, %1;" : "=f"(r) : "f"(x)); return r;
}

__device__ __forceinline__ void flux1(float R, float M, float& V, float& F)
{
    const float LGC12 = -15.287712379549449f;   // lg2(C1^2), C1 = DT/(2*DX)
    float rinv = xrcp(R);
    V = M * rinv;                               // C1 * v
    float Pp = xex2(fmaf(1.4f, xlg2(R), LGC12)); // C1^2 * rho^1.4
    F = fmaf(M, V, Pp);                         // C1^2 * (rho v^2 + P)
}

// One LxF step; SL/SF are compile-time-selected edge buffers.
__device__ __forceinline__ void lxf_step(float R[PPT], float Ms[PPT],
                                         float4* __restrict__ SL,
                                         float4* __restrict__ SF,
                                         int t, int lt, int rt)
{
    float Vs[PPT], FPs[PPT];

    // boundary fluxes first, publish immediately
    flux1(R[0],       Ms[0],       Vs[0],       FPs[0]);
    flux1(R[PPT - 1], Ms[PPT - 1], Vs[PPT - 1], FPs[PPT - 1]);
    SL[t] = make_float4(R[PPT - 1], Ms[PPT - 1], Vs[PPT - 1], FPs[PPT - 1]);
    SF[t] = make_float4(R[0],       Ms[0],       Vs[0],       FPs[0]);

    // interior fluxes
    #pragma unroll
    for (int j = 1; j < PPT - 1; ++j)
        flux1(R[j], Ms[j], Vs[j], FPs[j]);

    __syncthreads();

    float4 eL = SL[lt];   // neighbor's last cell  (my cell -1)
    float4 eR = SF[rt];   // neighbor's first cell (my cell +PPT)

    // pass 2: update on scaled (R, Ms)
    float pR = eL.x, pM = eL.y, pV = eL.z, pF = eL.w;
    #pragma unroll
    for (int j = 0; j < PPT; ++j) {
        const bool last = (j == PPT - 1);           // compile-time
        float nR = last ? eR.x : R[j + 1];
        float nM = last ? eR.y : Ms[j + 1];
        float nV = last ? eR.z : Vs[j + 1];
        float nF = last ? eR.w : FPs[j + 1];

        float dM    = nM - pM;
        float rnew  = fmaf(0.5f, nR + pR, -dM);

        float visc  = fmaf(-2.0f, Vs[j], nV + pV);  // C1*(vn+vp-2v)

        float dF    = nF - pF;
        float m0    = fmaf(0.5f, nM + pM, -dF);
        float msnew = fmaf(0.01f * R[j], visc, m0); // C2 = DT*MU/DX^2

        pR = R[j]; pM = Ms[j]; pV = Vs[j]; pF = FPs[j];
        R[j] = rnew; Ms[j] = msnew;
    }
}

__global__ __launch_bounds__(NT, 2)
void obf_solver_kernel(const float* __restrict__ rho0,
                       const float* __restrict__ v0,
                       const int*   __restrict__ n_steps_ptr,
                       float*       __restrict__ out,
                       int N, int stride)
{
    // Two statically-selected edge buffers: [0]=Last-cell, [1]=First-cell.
    __shared__ float4 S0[2][NT];
    __shared__ float4 S1[2][NT];

    const int t = threadIdx.x;
    const int b = blockIdx.x;
    const int base = b * stride - HALO + t * PPT;

    const float C1    = 0.005f;
    const float INVC1 = 200.0f;

    float R[PPT], Ms[PPT];

    // ---- load initial state (periodic wrap); Ms = C1 * rho * v ----
    #pragma unroll
    for (int j = 0; j < PPT; ++j) {
        int g = base + j + N;
        if (g >= N) g -= N;
        if (g >= N) g -= N;
        float r = rho0[g];
        float v = v0[g];
        R[j]  = r;
        Ms[j] = (C1 * r) * v;
    }

    const int n_steps = *n_steps_ptr;

    const int lt = (t == 0)      ? 0      : t - 1;
    const int rt = (t == NT - 1) ? NT - 1 : t + 1;

    int s = 0;
    for (; s + 1 < n_steps; s += 2) {
        lxf_step(R, Ms, S0[0], S0[1], t, lt, rt);   // parity 0
        lxf_step(R, Ms, S1[0], S1[1], t, lt, rt);   // parity 1
    }
    if (s < n_steps) {
        lxf_step(R, Ms, S0[0], S0[1], t, lt, rt);
    }

    // ---- store valid interior: rho and v = (Ms/C1)/max(rho,1e-10) ----
    float* orho = out;
    float* ov   = out + N;
    #pragma unroll
    for (int j = 0; j < PPT; ++j) {
        int l = t * PPT + j;                 // local index in [0, LBUF)
        if (l >= HALO && l < LBUF - HALO) {
            int g = b * stride + (l - HALO);
            if (g >= N) g -= N;
            orho[g] = R[j];
            ov[g]   = (INVC1 * Ms[j]) * xrcp(fmaxf(R[j], 1e-10f));
        }
    }
}

extern "C" void kernel_launch(void* const* d_in, const int* in_sizes, int n_in,
                              void* d_out, int out_size)
{
    const float* rho0   = (const float*)d_in[0];
    const float* v0     = (const float*)d_in[1];
    const int*   nsteps = (const int*)d_in[2];
    float*       out    = (float*)d_out;

    const int N = in_sizes[0];
    int grid = GRID;
    if ((long long)grid * TILE < N)                 // safety for other shapes
        grid = (N + TILE - 1) / TILE;
    int stride = (N + grid - 1) / grid;             // 3543 <= TILE here

    obf_solver_kernel<<<grid, NT>>>(rho0, v0, nsteps, out, N, stride);
}

// round 12
// speedup vs baseline: 1.0869x; 1.0869x over previous
#include <cuda_runtime.h>

// Temporal-blocked persistent solver, R10 (second resubmit — rounds 10 and 11
// were broker/container infra failures; kernel never executed): merged rolling
// flux+update pass.
//  - NT=256, PPT=15 -> LBUF=3840, HALO=128/side, TILE=3584, GRID=296,
//    stride=3543 (perfect balance, occ 2).  [R8 geometry, the empirical best]
//  - C1-scaled conservative state: R=rho, Ms=C1*mom; derived V=C1*v,
//    F=C1^2*(rho v^2+P); C1^2 folded into the pow constant.
//  - KEY CHANGE vs R8: no Vs[]/FPs[] arrays. Fluxes are computed in a rolling
//    3-cell window fused with the update loop -> live registers drop from
//    ~120 to ~70, giving ptxas headroom to pipeline the MUFU chains.
//  - Static-parity double buffering (time loop unrolled x2), float4 edges,
//    ONE __syncthreads per step.
//  - No clamps in hot loop; halo garbage advances 1 cell/step, never reaches
//    the stored interior.

#define NT   256
#define PPT  15
#define LBUF (NT * PPT)            // 3840
#define HALO 128
#define TILE (LBUF - 2 * HALO)     // 3584
#define GRID 296

__device__ __forceinline__ float xlg2(float x) {
    float r; asm("lg2.approx.f32 %0, %1;" : "=f"(r) : "f"(x)); return r;
}
__device__ __forceinline__ float xex2(float x) {
    float r; asm("ex2.approx.f32 %0, %1;" : "=f"(r) : "f"(x)); return r;
}
__device__ __forceinline__ float xrcp(float x) {
    float r; asm("rcp.approx.f32 %0, %1;" : "=f"(r) : "f"(x)); return r;
}

// Flux for one cell: V = C1*v, F = C1^2*(rho v^2 + P)
__device__ __forceinline__ void flux1(float R, float M, float& V, float& F)
{
    const float LGC12 = -15.287712379549449f;    // lg2(C1^2), C1 = DT/(2*DX)
    float rinv = xrcp(R);
    V = M * rinv;
    float Pp = xex2(fmaf(1.4f, xlg2(R), LGC12)); // C1^2 * rho^1.4
    F = fmaf(M, V, Pp);
}

// One LxF step; SL/SF are compile-time-selected edge buffers.
__device__ __forceinline__ void lxf_step(float R[PPT], float Ms[PPT],
                                         float4* __restrict__ SL,
                                         float4* __restrict__ SF,
                                         int t, int lt, int rt)
{
    // boundary fluxes (computed once, published, and reused below)
    float V0, F0, VL, FL;
    flux1(R[0],       Ms[0],       V0, F0);
    flux1(R[PPT - 1], Ms[PPT - 1], VL, FL);
    SL[t] = make_float4(R[PPT - 1], Ms[PPT - 1], VL, FL);
    SF[t] = make_float4(R[0],       Ms[0],       V0, F0);
    __syncthreads();

    float4 eL = SL[lt];   // neighbor's last cell  (my cell -1)
    float4 eR = SF[rt];   // neighbor's first cell (my cell +PPT)

    // rolling window: p = cell j-1 (old), c = cell j (old), n = cell j+1 (old)
    float pR = eL.x, pM = eL.y, pV = eL.z, pF = eL.w;
    float cR = R[0], cM = Ms[0], cV = V0, cF = F0;

    #pragma unroll
    for (int j = 0; j < PPT; ++j) {
        float nR, nM, nV, nF;
        if (j == PPT - 1)      { nR = eR.x;       nM = eR.y;        nV = eR.z; nF = eR.w; }
        else if (j == PPT - 2) { nR = R[PPT - 1]; nM = Ms[PPT - 1]; nV = VL;   nF = FL; }
        else {
            nR = R[j + 1]; nM = Ms[j + 1];
            flux1(nR, nM, nV, nF);
        }

        float rnew  = fmaf(0.5f, nR + pR, pM - nM);
        float visc  = fmaf(-2.0f, cV, nV + pV);            // C1*(vn+vp-2v)
        float m0    = fmaf(0.5f, nM + pM, pF - nF);
        float msnew = fmaf(0.01f * cR, visc, m0);          // C2 = DT*MU/DX^2

        R[j] = rnew; Ms[j] = msnew;

        pR = cR; pM = cM; pV = cV; pF = cF;
        cR = nR; cM = nM; cV = nV; cF = nF;
    }
}

__global__ __launch_bounds__(NT, 2)
void obf_solver_kernel(const float* __restrict__ rho0,
                       const float* __restrict__ v0,
                       const int*   __restrict__ n_steps_ptr,
                       float*       __restrict__ out,
                       int N, int stride)
{
    // Two statically-selected edge buffers: [0]=Last-cell, [1]=First-cell.
    __shared__ float4 S0[2][NT];
    __shared__ float4 S1[2][NT];

    const int t = threadIdx.x;
    const int b = blockIdx.x;
    const int base = b * stride - HALO + t * PPT;

    const float C1    = 0.005f;
    const float INVC1 = 200.0f;

    float R[PPT], Ms[PPT];

    // ---- load initial state (periodic wrap); Ms = C1 * rho * v ----
    #pragma unroll
    for (int j = 0; j < PPT; ++j) {
        int g = base + j + N;
        if (g >= N) g -= N;
        if (g >= N) g -= N;
        float r = rho0[g];
        float v = v0[g];
        R[j]  = r;
        Ms[j] = (C1 * r) * v;
    }

    const int n_steps = *n_steps_ptr;

    const int lt = (t == 0)      ? 0      : t - 1;
    const int rt = (t == NT - 1) ? NT - 1 : t + 1;

    int s = 0;
    for (; s + 1 < n_steps; s += 2) {
        lxf_step(R, Ms, S0[0], S0[1], t, lt, rt);   // parity 0
        lxf_step(R, Ms, S1[0], S1[1], t, lt, rt);   // parity 1
    }
    if (s < n_steps) {
        lxf_step(R, Ms, S0[0], S0[1], t, lt, rt);
    }

    // ---- store valid interior: rho and v = (Ms/C1)/max(rho,1e-10) ----
    float* orho = out;
    float* ov   = out + N;
    #pragma unroll
    for (int j = 0; j < PPT; ++j) {
        int l = t * PPT + j;                 // local index in [0, LBUF)
        if (l >= HALO && l < LBUF - HALO) {
            int g = b * stride + (l - HALO);
            if (g >= N) g -= N;
            orho[g] = R[j];
            ov[g]   = (INVC1 * Ms[j]) * xrcp(fmaxf(R[j], 1e-10f));
        }
    }
}

extern "C" void kernel_launch(void* const* d_in, const int* in_sizes, int n_in,
                              void* d_out, int out_size)
{
    const float* rho0   = (const float*)d_in[0];
    const float* v0     = (const float*)d_in[1];
    const int*   nsteps = (const int*)d_in[2];
    float*       out    = (float*)d_out;

    const int N = in_sizes[0];
    int grid = GRID;
    if ((long long)grid * TILE < N)                 // safety for other shapes
        grid = (N + TILE - 1) / TILE;
    int stride = (N + grid - 1) / grid;             // 3543 <= TILE here

    obf_solver_kernel<<<grid, NT>>>(rho0, v0, nsteps, out, N, stride);
}